// round 9
// baseline (speedup 1.0000x reference)
#include <cuda_runtime.h>
#include <cuda_fp16.h>
#include <cstdint>

// ---------------- problem constants ----------------
#define NSUP 25
#define NQ 400
#define SEQF 8
#define DIM 2048
#define DOUT 1024
#define TN 56
#define NWAY 5
#define SHOT 5
#define SACT 280            // shot*Tn real supports per class
#define SPACK 1408          // 5*280 packed + 8 pad = 11 x 128 tiles
#define NT3 (SPACK/128)     // 11 N-tiles in gemm3
#define QROWS 22400         // 400*56
#define QPAD 22528          // 176 x 128
#define MFR 3200            // query frames
#define MPAD 3584           // 28 x 128

// ---------------- MMA smem layout (128x128 CTA tile, 128B rows, 3 stages) ----------------
#define TILE_BYTES 16384                   // 128 rows x 128B
#define STAGE_BYTES (2*TILE_BYTES)         // A + B = 32 KB
#define SMEM_BYTES (3*STAGE_BYTES)         // 96 KB -> 2 CTAs/SM
#define SWZ(o) ((o) ^ (((o) >> 3) & 0x70))

// assembly smem: 24 vectors of 1024 fp16 + reduce scratch
#define ASM_SMEM (24*1024*2 + (TN*8 + 16)*4)

// combinations(range(8),3), lexicographic
__constant__ unsigned char TUP[TN][3] = {
  {0,1,2},{0,1,3},{0,1,4},{0,1,5},{0,1,6},{0,1,7},
  {0,2,3},{0,2,4},{0,2,5},{0,2,6},{0,2,7},
  {0,3,4},{0,3,5},{0,3,6},{0,3,7},
  {0,4,5},{0,4,6},{0,4,7},
  {0,5,6},{0,5,7},{0,6,7},
  {1,2,3},{1,2,4},{1,2,5},{1,2,6},{1,2,7},
  {1,3,4},{1,3,5},{1,3,6},{1,3,7},
  {1,4,5},{1,4,6},{1,4,7},
  {1,5,6},{1,5,7},{1,6,7},
  {2,3,4},{2,3,5},{2,3,6},{2,3,7},
  {2,4,5},{2,4,6},{2,4,7},
  {2,5,6},{2,5,7},{2,6,7},
  {3,4,5},{3,4,6},{3,4,7},
  {3,5,6},{3,5,7},{3,6,7},
  {4,5,6},{4,5,7},{4,6,7},
  {5,6,7}
};

// class -> 3 (tile,half) entries; entry e: tile = e>>1, half = e&1
__constant__ unsigned char CLS_E[NWAY][3] = {
  {0, 2, 4}, {5, 6, 8}, {9, 10, 12}, {13, 14, 16}, {17, 18, 20}
};

// ---------------- scratch (__device__ globals) ----------------
__device__ __align__(256) __half  g_Ah[(size_t)MPAD*DIM];         // frames fp16
__device__ __align__(256) __half  g_Wh[(size_t)3*DOUT*DIM];       // W rearranged fp16
__device__ __align__(256) float   g_P[(size_t)MPAD*3*DOUT];       // partial embeddings
__device__ __align__(256) int8_t  g_QEq[(size_t)QPAD*DOUT];       // query tuple emb int8
__device__ __align__(256) float   g_q2[QPAD];
__device__ __align__(256) float   g_qs[QPAD];                     // per-row dequant scale
__device__ __align__(256) int8_t  g_SEq[(size_t)SPACK*DOUT];      // packed support emb int8
__device__ __align__(256) float   g_s2[SPACK];
__device__ __align__(256) float   g_ss[SPACK];
__device__ __align__(256) float   g_tmin[2*NT3][QPAD];            // per-(tile,half) row mins
__device__ int g_clsidx[NWAY*SHOT];
__device__ int g_sloc[NSUP];                                      // support n -> c*SHOT+shotRank

// ---------------- helpers ----------------
__device__ __forceinline__ uint32_t smem_u32(const void* p) {
    uint32_t a;
    asm("{ .reg .u64 t; cvta.to.shared.u64 t, %1; cvt.u32.u64 %0, t; }" : "=r"(a) : "l"(p));
    return a;
}
__device__ __forceinline__ void cp16(uint32_t s, const void* g) {
    asm volatile("cp.async.cg.shared.global [%0], [%1], 16;" :: "r"(s), "l"(g) : "memory");
}
#define LDSM4(r, addr) \
    asm volatile("ldmatrix.sync.aligned.m8n8.x4.shared.b16 {%0,%1,%2,%3}, [%4];" \
        : "=r"((r)[0]), "=r"((r)[1]), "=r"((r)[2]), "=r"((r)[3]) : "r"(addr))
#define MMA_F16(c, a, b0, b1) \
    asm volatile("mma.sync.aligned.m16n8k16.row.col.f32.f16.f16.f32 " \
        "{%0,%1,%2,%3}, {%4,%5,%6,%7}, {%8,%9}, {%0,%1,%2,%3};" \
        : "+f"((c)[0]), "+f"((c)[1]), "+f"((c)[2]), "+f"((c)[3]) \
        : "r"((a)[0]), "r"((a)[1]), "r"((a)[2]), "r"((a)[3]), "r"(b0), "r"(b1))
#define MMA_S8(c, a, b0, b1) \
    asm volatile("mma.sync.aligned.m16n8k32.row.col.s32.s8.s8.s32 " \
        "{%0,%1,%2,%3}, {%4,%5,%6,%7}, {%8,%9}, {%0,%1,%2,%3};" \
        : "+r"((c)[0]), "+r"((c)[1]), "+r"((c)[2]), "+r"((c)[3]) \
        : "r"((a)[0]), "r"((a)[1]), "r"((a)[2]), "r"((a)[3]), "r"(b0), "r"(b1))

// ---------------- fp16 mainloop (gemm1): CTA 128x128, K-chunk 64 ----------------
__device__ __forceinline__ void load_tile_h(uint32_t sbase, const __half* g,
                                            int stride, int chunk, int tid) {
    const __half* gp = g + (size_t)chunk * 64;
    #pragma unroll
    for (int i = 0; i < 4; i++) {
        int idx = i * 256 + tid;
        int row = idx >> 3, seg = idx & 7;
        cp16(sbase + SWZ(row * 128 + seg * 16), gp + (size_t)row * stride + seg * 8);
    }
}
__device__ __forceinline__ void load_stage_h(uint32_t sbase, const __half* A, const __half* B,
                                             int stride, int chunk, int tid) {
    load_tile_h(sbase, A, stride, chunk, tid);
    load_tile_h(sbase + TILE_BYTES, B, stride, chunk, tid);
}

template<int KC>
__device__ __forceinline__ void mma_mainloop_h(
    const __half* A, const __half* B, int stride, char* smem, float acc[4][4][4])
{
    const uint32_t sb = smem_u32(smem);
    const int tid = threadIdx.x;
    const int l = tid & 31;
    const int wm = (tid >> 5) >> 2, wn = (tid >> 5) & 3;

    load_stage_h(sb, A, B, stride, 0, tid);
    asm volatile("cp.async.commit_group;" ::: "memory");
    load_stage_h(sb + STAGE_BYTES, A, B, stride, 1, tid);
    asm volatile("cp.async.commit_group;" ::: "memory");

    const uint32_t aRowB = (uint32_t)(wm * 64 + (l & 15)) * 128;
    const uint32_t aXm   = (uint32_t)(l & 7) << 4;
    const uint32_t aK    = ((l >> 4) & 1) * 16;
    const uint32_t bRowB = (uint32_t)(wn * 32 + (l & 7) + ((l >> 4) & 1) * 8) * 128;
    const uint32_t bXm   = (uint32_t)(l & 7) << 4;
    const uint32_t bK    = ((l >> 3) & 1) * 16;

    int stCur = 0, stNxt = 2;
    #pragma unroll 1
    for (int k = 0; k < KC; k++) {
        if (k + 2 < KC) { asm volatile("cp.async.wait_group 1;" ::: "memory"); }
        else            { asm volatile("cp.async.wait_group 0;" ::: "memory"); }
        __syncthreads();
        if (k + 2 < KC) {
            load_stage_h(sb + (uint32_t)stNxt * STAGE_BYTES, A, B, stride, k + 2, tid);
            asm volatile("cp.async.commit_group;" ::: "memory");
        }
        const uint32_t st = sb + (uint32_t)stCur * STAGE_BYTES;
        #pragma unroll
        for (int kk = 0; kk < 4; kk++) {
            uint32_t a[4][4], b[8];
            const uint32_t ao = ((kk * 32 + aK) ^ aXm) + aRowB;
            const uint32_t bo = ((kk * 32 + bK) ^ bXm) + bRowB + TILE_BYTES;
            #pragma unroll
            for (int mi = 0; mi < 4; mi++) LDSM4(a[mi], st + ao + mi * 2048);
            LDSM4(b + 0, st + bo);
            LDSM4(b + 4, st + bo + 2048);
            #pragma unroll
            for (int mi = 0; mi < 4; mi++)
                #pragma unroll
                for (int ni = 0; ni < 4; ni++)
                    MMA_F16(acc[mi][ni], a[mi], b[ni * 2], b[ni * 2 + 1]);
        }
        stCur = (stCur == 2) ? 0 : stCur + 1;
        stNxt = (stNxt == 2) ? 0 : stNxt + 1;
    }
    __syncthreads();
}

// ---------------- int8 mainloop (gemm3): CTA 128x128, K-chunk 128 bytes ----------------
// s8 m16n8k32 fragments are byte-pair identical to f16 m16n8k16 fragments,
// so ldmatrix addressing is unchanged; each 128B row now holds 128 k-elems.
__device__ __forceinline__ void load_tile_8(uint32_t sbase, const int8_t* g,
                                            int stride, int chunk, int tid) {
    const int8_t* gp = g + chunk * 128;
    #pragma unroll
    for (int i = 0; i < 4; i++) {
        int idx = i * 256 + tid;
        int row = idx >> 3, seg = idx & 7;
        cp16(sbase + SWZ(row * 128 + seg * 16), gp + (size_t)row * stride + seg * 16);
    }
}
__device__ __forceinline__ void load_stage_8(uint32_t sbase, const int8_t* A, const int8_t* B,
                                             int stride, int chunk, int tid) {
    load_tile_8(sbase, A, stride, chunk, tid);
    load_tile_8(sbase + TILE_BYTES, B, stride, chunk, tid);
}

template<int KC>   // chunks of 128 int8
__device__ __forceinline__ void mma_mainloop_8(
    const int8_t* A, const int8_t* B, int stride, char* smem, int acc[4][4][4])
{
    const uint32_t sb = smem_u32(smem);
    const int tid = threadIdx.x;
    const int l = tid & 31;
    const int wm = (tid >> 5) >> 2, wn = (tid >> 5) & 3;

    load_stage_8(sb, A, B, stride, 0, tid);
    asm volatile("cp.async.commit_group;" ::: "memory");
    load_stage_8(sb + STAGE_BYTES, A, B, stride, 1, tid);
    asm volatile("cp.async.commit_group;" ::: "memory");

    const uint32_t aRowB = (uint32_t)(wm * 64 + (l & 15)) * 128;
    const uint32_t aXm   = (uint32_t)(l & 7) << 4;
    const uint32_t aK    = ((l >> 4) & 1) * 16;
    const uint32_t bRowB = (uint32_t)(wn * 32 + (l & 7) + ((l >> 4) & 1) * 8) * 128;
    const uint32_t bXm   = (uint32_t)(l & 7) << 4;
    const uint32_t bK    = ((l >> 3) & 1) * 16;

    int stCur = 0, stNxt = 2;
    #pragma unroll 1
    for (int k = 0; k < KC; k++) {
        if (k + 2 < KC) { asm volatile("cp.async.wait_group 1;" ::: "memory"); }
        else            { asm volatile("cp.async.wait_group 0;" ::: "memory"); }
        __syncthreads();
        if (k + 2 < KC) {
            load_stage_8(sb + (uint32_t)stNxt * STAGE_BYTES, A, B, stride, k + 2, tid);
            asm volatile("cp.async.commit_group;" ::: "memory");
        }
        const uint32_t st = sb + (uint32_t)stCur * STAGE_BYTES;
        #pragma unroll
        for (int kk = 0; kk < 4; kk++) {
            uint32_t a[4][4], b[8];
            const uint32_t ao = ((kk * 32 + aK) ^ aXm) + aRowB;
            const uint32_t bo = ((kk * 32 + bK) ^ bXm) + bRowB + TILE_BYTES;
            #pragma unroll
            for (int mi = 0; mi < 4; mi++) LDSM4(a[mi], st + ao + mi * 2048);
            LDSM4(b + 0, st + bo);
            LDSM4(b + 4, st + bo + 2048);
            #pragma unroll
            for (int mi = 0; mi < 4; mi++)
                #pragma unroll
                for (int ni = 0; ni < 4; ni++)
                    MMA_S8(acc[mi][ni], a[mi], b[ni * 2], b[ni * 2 + 1]);
        }
        stCur = (stCur == 2) ? 0 : stCur + 1;
        stNxt = (stNxt == 2) ? 0 : stNxt + 1;
    }
    __syncthreads();
}

// ---------------- stage 0: label decode ----------------
__global__ void build_clsmap(const int* __restrict__ raw)
{
    if (threadIdx.x != 0 || blockIdx.x != 0) return;
    bool is64 = true;
    for (int i = 1; i < NSUP; i += 2) if (raw[i] != 0) { is64 = false; break; }
    if (is64) for (int i = 0; i < NSUP; i += 2) if (raw[i] < 0 || raw[i] >= NWAY) { is64 = false; break; }
    int cnt[NWAY];
    #pragma unroll
    for (int c = 0; c < NWAY; ++c) cnt[c] = 0;
    for (int i = 0; i < NSUP; ++i) {
        int lab = is64 ? raw[2 * i] : raw[i];
        if (lab >= 0 && lab < NWAY && cnt[lab] < SHOT) {
            g_clsidx[lab * SHOT + cnt[lab]] = i;
            g_sloc[i] = lab * SHOT + cnt[lab];
            cnt[lab]++;
        }
    }
}

// ---------------- merged conversion kernel ----------------
__device__ __forceinline__ uint2 pack_half4(float4 r) {
    __half h0 = __float2half_rn(r.x), h1 = __float2half_rn(r.y),
           h2 = __float2half_rn(r.z), h3 = __float2half_rn(r.w);
    uint2 p;
    p.x = (uint32_t)__half_as_ushort(h0) | ((uint32_t)__half_as_ushort(h1) << 16);
    p.y = (uint32_t)__half_as_ushort(h2) | ((uint32_t)__half_as_ushort(h3) << 16);
    return p;
}

#define NQ4 (MFR * DIM / 4)                 // query quads
#define NS4 ((MPAD - MFR) * DIM / 4)        // support + pad quads
#define NW4 (3 * DOUT * DIM / 4)            // W quads

__global__ __launch_bounds__(256) void convAll(const float* __restrict__ q,
                                               const float* __restrict__ s,
                                               const float* __restrict__ W)
{
    int i = blockIdx.x * 256 + threadIdx.x;
    if (i < NQ4) {
        *(uint2*)(g_Ah + (size_t)i * 4) = pack_half4(((const float4*)q)[i]);
    } else if (i < NQ4 + NS4) {
        i -= NQ4;
        uint2 p = make_uint2(0, 0);
        if (i < NSUP * SEQF * DIM / 4) p = pack_half4(((const float4*)s)[i]);
        *(uint2*)(g_Ah + (size_t)MFR * DIM + (size_t)i * 4) = p;
    } else if (i < NQ4 + NS4 + NW4) {
        i -= NQ4 + NS4;
        size_t e = (size_t)i * 4;
        int k = (int)(e & (DIM - 1));
        size_t r = e >> 11;
        int n = (int)(r & (DOUT - 1));
        int j = (int)(r >> 10);
        float4 x = *(const float4*)(W + (size_t)n * (3 * DIM) + (size_t)j * DIM + k);
        *(uint2*)(g_Wh + e) = pack_half4(x);
    }
}

// ---------------- stage 1: partial-embedding GEMM (fp16) ----------------
__global__ __launch_bounds__(256, 2) void gemm1()
{
    extern __shared__ char smem[];
    const int nBase = blockIdx.x * 128;
    const int j     = blockIdx.y;
    const int mBase = blockIdx.z * 128;
    float acc[4][4][4];
    #pragma unroll
    for (int a = 0; a < 4; a++)
        #pragma unroll
        for (int b = 0; b < 4; b++)
            #pragma unroll
            for (int c = 0; c < 4; c++) acc[a][b][c] = 0.f;

    mma_mainloop_h<DIM / 64>(
        g_Ah + (size_t)mBase * DIM,
        g_Wh + ((size_t)j * DOUT + nBase) * DIM,
        DIM, smem, acc);

    const int tid = threadIdx.x, l = tid & 31;
    const int wm = (tid >> 5) >> 2, wn = (tid >> 5) & 3;
    #pragma unroll
    for (int mi = 0; mi < 4; mi++) {
        const int r0 = mBase + wm * 64 + mi * 16 + (l >> 2);
        #pragma unroll
        for (int ni = 0; ni < 4; ni++) {
            const int col = nBase + wn * 32 + ni * 8 + (l & 3) * 2;
            *(float2*)(g_P + ((size_t)r0 * 3 + j) * DOUT + col) =
                make_float2(acc[mi][ni][0], acc[mi][ni][1]);
            *(float2*)(g_P + ((size_t)(r0 + 8) * 3 + j) * DOUT + col) =
                make_float2(acc[mi][ni][2], acc[mi][ni][3]);
        }
    }
}

// ---------------- stage 2: fused per-video assembly + int8 quantization ----------------
__device__ __forceinline__ float4 tuple_val(const __half* sP, int t, int o, float4 vb) {
    const int f0 = TUP[t][0], f1 = TUP[t][1], f2 = TUP[t][2];
    uint2 pa = *(const uint2*)(sP + (f0 * 3 + 0) * DOUT + o);
    uint2 pb = *(const uint2*)(sP + (f1 * 3 + 1) * DOUT + o);
    uint2 pc = *(const uint2*)(sP + (f2 * 3 + 2) * DOUT + o);
    float2 a0 = __half22float2(*(__half2*)&pa.x), a1 = __half22float2(*(__half2*)&pa.y);
    float2 b0 = __half22float2(*(__half2*)&pb.x), b1 = __half22float2(*(__half2*)&pb.y);
    float2 c0 = __half22float2(*(__half2*)&pc.x), c1 = __half22float2(*(__half2*)&pc.y);
    float4 r;
    r.x = fmaxf(a0.x + b0.x + c0.x + vb.x, 0.f);
    r.y = fmaxf(a0.y + b0.y + c0.y + vb.y, 0.f);
    r.z = fmaxf(a1.x + b1.x + c1.x + vb.z, 0.f);
    r.w = fmaxf(a1.y + b1.y + c1.y + vb.w, 0.f);
    return r;
}

__device__ __forceinline__ void assemble_video(
    const float* __restrict__ srcP,     // 24 rows x 1024 fp32 (contiguous)
    int8_t* __restrict__ dstE,          // first of 56 int8 output rows
    float* __restrict__ dstN,           // 56 norms
    float* __restrict__ dstS,           // 56 scales
    const float* __restrict__ bias,
    char* smemRaw)
{
    __half* sP = (__half*)smemRaw;                       // 24*1024 fp16
    float* ws = (float*)(smemRaw + 24 * 1024 * 2);       // TN*8
    float* sred = ws + TN * 8;                           // 9 floats
    const int tid = threadIdx.x;
    #pragma unroll
    for (int i = 0; i < 24; i++) {
        float4 v = *(const float4*)(srcP + i * DOUT + tid * 4);
        *(uint2*)(sP + i * DOUT + tid * 4) = pack_half4(v);
    }
    __syncthreads();
    const int o = tid * 4;
    const float4 vb = *(const float4*)(bias + o);
    const int l = tid & 31, wid = tid >> 5;

    // pass 1: per-video max
    float mx = 0.f;
    #pragma unroll 4
    for (int t = 0; t < TN; t++) {
        float4 r = tuple_val(sP, t, o, vb);
        mx = fmaxf(fmaxf(mx, fmaxf(r.x, r.y)), fmaxf(r.z, r.w));
    }
    #pragma unroll
    for (int s = 16; s > 0; s >>= 1) mx = fmaxf(mx, __shfl_xor_sync(0xffffffffu, mx, s));
    if (l == 0) sred[wid] = mx;
    __syncthreads();
    if (tid == 0) {
        float m = sred[0];
        #pragma unroll
        for (int i = 1; i < 8; i++) m = fmaxf(m, sred[i]);
        sred[8] = m;
    }
    __syncthreads();
    const float mxAll = sred[8];
    const float scale = mxAll * (1.f / 127.f);
    const float inv = mxAll > 0.f ? 127.f / mxAll : 0.f;

    // pass 2: quantize + rounded norms
    #pragma unroll 4
    for (int t = 0; t < TN; t++) {
        float4 r = tuple_val(sP, t, o, vb);
        int i0 = __float2int_rn(r.x * inv), i1 = __float2int_rn(r.y * inv);
        int i2 = __float2int_rn(r.z * inv), i3 = __float2int_rn(r.w * inv);
        uint32_t pk = (uint32_t)(i0 & 255) | ((uint32_t)(i1 & 255) << 8) |
                      ((uint32_t)(i2 & 255) << 16) | ((uint32_t)(i3 & 255) << 24);
        *(uint32_t*)(dstE + (size_t)t * DOUT + o) = pk;
        float d0 = i0 * scale, d1 = i1 * scale, d2 = i2 * scale, d3 = i3 * scale;
        float ssq = d0 * d0 + d1 * d1 + d2 * d2 + d3 * d3;
        #pragma unroll
        for (int s = 16; s > 0; s >>= 1) ssq += __shfl_xor_sync(0xffffffffu, ssq, s);
        if (l == 0) ws[t * 8 + wid] = ssq;
    }
    __syncthreads();
    if (tid < TN) {
        float s = 0.f;
        #pragma unroll
        for (int i = 0; i < 8; i++) s += ws[tid * 8 + i];
        dstN[tid] = s;
        dstS[tid] = scale;
    }
}

__global__ __launch_bounds__(256) void assemble_q(const float* __restrict__ bias)
{
    extern __shared__ char sRaw[];
    const int q = blockIdx.x;
    const int tid = threadIdx.x;
    if (q >= NQ) {   // zero pad rows
        for (int i = tid; i < (QPAD - QROWS) * DOUT / 8; i += 256)
            *(uint2*)(g_QEq + (size_t)QROWS * DOUT + (size_t)i * 8) = make_uint2(0, 0);
        for (int i = tid; i < QPAD - QROWS; i += 256) { g_q2[QROWS + i] = 0.f; g_qs[QROWS + i] = 0.f; }
        return;
    }
    assemble_video(g_P + (size_t)q * 24 * DOUT,
                   g_QEq + (size_t)q * TN * DOUT,
                   g_q2 + q * TN, g_qs + q * TN, bias, sRaw);
}

__global__ __launch_bounds__(256) void assemble_s(const float* __restrict__ bias)
{
    extern __shared__ char sRaw[];
    const int n = blockIdx.x;
    const int tid = threadIdx.x;
    if (n >= NSUP) {  // pad cols 1400..1407
        for (int i = tid; i < (SPACK - NWAY * SACT) * DOUT / 8; i += 256)
            *(uint2*)(g_SEq + (size_t)NWAY * SACT * DOUT + (size_t)i * 8) = make_uint2(0, 0);
        if (tid < SPACK - NWAY * SACT) { g_s2[NWAY * SACT + tid] = 1e30f; g_ss[NWAY * SACT + tid] = 0.f; }
        return;
    }
    const int loc = g_sloc[n];                    // c*SHOT + shotRank
    const int base = (loc / SHOT) * SACT + (loc % SHOT) * TN;
    assemble_video(g_P + (size_t)(MFR + n * SEQF) * 3 * DOUT,
                   g_SEq + (size_t)base * DOUT,
                   g_s2 + base, g_ss + base, bias, sRaw);
}

// ---------------- stage 3: int8 distance GEMM + per-tile class-half min ----------------
__global__ __launch_bounds__(256, 2) void gemm3()
{
    extern __shared__ char smem[];
    __shared__ float s2s[128], sss[128], sqs[128];
    __shared__ float rowmin[128][4][2];
    const int nt    = blockIdx.x;                // packed support tile
    const int nBase = nt * 128;
    const int mBase = blockIdx.y * 128;
    const int tid = threadIdx.x, l = tid & 31;
    const int wm = (tid >> 5) >> 2, wn = (tid >> 5) & 3;

    if (tid < 128) {
        s2s[tid] = g_s2[nBase + tid];
        sss[tid] = g_ss[nBase + tid];
        sqs[tid] = g_qs[mBase + tid];
    }

    int acc[4][4][4];
    #pragma unroll
    for (int a = 0; a < 4; a++)
        #pragma unroll
        for (int b = 0; b < 4; b++)
            #pragma unroll
            for (int d = 0; d < 4; d++) acc[a][b][d] = 0;

    mma_mainloop_8<DOUT / 128>(
        g_QEq + (size_t)mBase * DOUT,
        g_SEq + (size_t)nBase * DOUT,
        DOUT, smem, acc);

    // segmented epilogue: tile spans at most 2 classes (boundary is even)
    const int cLo = min(nBase / SACT, NWAY - 1);
    float mnL0[4], mnL1[4], mnH0[4], mnH1[4];
    #pragma unroll
    for (int mi = 0; mi < 4; mi++) { mnL0[mi] = 3e38f; mnL1[mi] = 3e38f; mnH0[mi] = 3e38f; mnH1[mi] = 3e38f; }
    #pragma unroll
    for (int ni = 0; ni < 4; ni++) {
        const int col = wn * 32 + ni * 8 + (l & 3) * 2;
        const bool isHi = (min((nBase + col) / SACT, NWAY - 1) != cLo);
        const float sa = s2s[col], sbv = s2s[col + 1];
        const float ts0 = 2.f * sss[col], ts1 = 2.f * sss[col + 1];
        #pragma unroll
        for (int mi = 0; mi < 4; mi++) {
            const int rl = wm * 64 + mi * 16 + (l >> 2);
            const float q0 = sqs[rl], q8 = sqs[rl + 8];
            float v0 = fminf(fmaf(-q0 * ts0, (float)acc[mi][ni][0], sa),
                             fmaf(-q0 * ts1, (float)acc[mi][ni][1], sbv));
            float v1 = fminf(fmaf(-q8 * ts0, (float)acc[mi][ni][2], sa),
                             fmaf(-q8 * ts1, (float)acc[mi][ni][3], sbv));
            if (isHi) { mnH0[mi] = fminf(mnH0[mi], v0); mnH1[mi] = fminf(mnH1[mi], v1); }
            else      { mnL0[mi] = fminf(mnL0[mi], v0); mnL1[mi] = fminf(mnL1[mi], v1); }
        }
    }
    #pragma unroll
    for (int mi = 0; mi < 4; mi++) {
        #pragma unroll
        for (int s = 1; s <= 2; s <<= 1) {
            mnL0[mi] = fminf(mnL0[mi], __shfl_xor_sync(0xffffffffu, mnL0[mi], s));
            mnL1[mi] = fminf(mnL1[mi], __shfl_xor_sync(0xffffffffu, mnL1[mi], s));
            mnH0[mi] = fminf(mnH0[mi], __shfl_xor_sync(0xffffffffu, mnH0[mi], s));
            mnH1[mi] = fminf(mnH1[mi], __shfl_xor_sync(0xffffffffu, mnH1[mi], s));
        }
    }
    if ((l & 3) == 0) {
        #pragma unroll
        for (int mi = 0; mi < 4; mi++) {
            const int r0 = wm * 64 + mi * 16 + (l >> 2);
            rowmin[r0][wn][0] = mnL0[mi];      rowmin[r0][wn][1] = mnH0[mi];
            rowmin[r0 + 8][wn][0] = mnL1[mi];  rowmin[r0 + 8][wn][1] = mnH1[mi];
        }
    }
    __syncthreads();
    if (tid < 128) {
        float mL = fminf(fminf(rowmin[tid][0][0], rowmin[tid][1][0]),
                         fminf(rowmin[tid][2][0], rowmin[tid][3][0]));
        float mH = fminf(fminf(rowmin[tid][0][1], rowmin[tid][1][1]),
                         fminf(rowmin[tid][2][1], rowmin[tid][3][1]));
        g_tmin[2 * nt + 0][mBase + tid] = mL;
        g_tmin[2 * nt + 1][mBase + tid] = mH;
    }
}

// ---------------- stage 4: finalize ----------------
__global__ void finalize(float* __restrict__ out)
{
    int idx = blockIdx.x * blockDim.x + threadIdx.x;
    if (idx >= NQ * NWAY) return;
    int q = idx / NWAY, c = idx % NWAY;
    const int e0 = CLS_E[c][0], e1 = CLS_E[c][1], e2 = CLS_E[c][2];
    float s = 0.f;
    #pragma unroll 8
    for (int t = 0; t < TN; ++t) {
        const int row = q * TN + t;
        float m = fminf(fminf(g_tmin[e0][row], g_tmin[e1][row]), g_tmin[e2][row]);
        s += sqrtf(fmaxf(g_q2[row] + m, 0.f));
    }
    out[q * NWAY + c] = -s * (1.0f / (float)TN);
}

// ---------------- launch ----------------
extern "C" void kernel_launch(void* const* d_in, const int* in_sizes, int n_in,
                              void* d_out, int out_size)
{
    const float* support = (const float*)d_in[0];      // [25,8,2048]
    const int*   labraw  = (const int*)d_in[1];        // [25] int32/int64
    const float* queries = (const float*)d_in[2];      // [400,8,2048]
    const float* W       = (const float*)d_in[3];      // [1024,6144]
    const float* bias    = (const float*)d_in[4];      // [1024]
    float*       out     = (float*)d_out;              // [400,5]
    (void)in_sizes; (void)n_in; (void)out_size;

    cudaFuncSetAttribute(gemm1, cudaFuncAttributeMaxDynamicSharedMemorySize, SMEM_BYTES);
    cudaFuncSetAttribute(gemm3, cudaFuncAttributeMaxDynamicSharedMemorySize, SMEM_BYTES);
    cudaFuncSetAttribute(assemble_q, cudaFuncAttributeMaxDynamicSharedMemorySize, ASM_SMEM);
    cudaFuncSetAttribute(assemble_s, cudaFuncAttributeMaxDynamicSharedMemorySize, ASM_SMEM);

    build_clsmap<<<1, 32>>>(labraw);

    convAll<<<(NQ4 + NS4 + NW4 + 255) / 256, 256>>>(queries, support, W);

    gemm1<<<dim3(DOUT / 128, 3, MPAD / 128), 256, SMEM_BYTES>>>();

    assemble_q<<<NQ + 1, 256, ASM_SMEM>>>(bias);
    assemble_s<<<NSUP + 1, 256, ASM_SMEM>>>(bias);

    gemm3<<<dim3(NT3, QPAD / 128), 256, SMEM_BYTES>>>();

    finalize<<<(NQ * NWAY + 255) / 256, 256>>>(out);
}

// round 10
// speedup vs baseline: 2.1240x; 2.1240x over previous
#include <cuda_runtime.h>
#include <cuda_fp16.h>
#include <cstdint>

// ---------------- problem constants ----------------
#define NSUP 25
#define NQ 400
#define SEQF 8
#define DIM 2048
#define DOUT 1024
#define TN 56
#define NWAY 5
#define SHOT 5
#define SACT 280            // shot*Tn real supports per class
#define SPACK 1408          // 5*280 packed + 8 pad = 11 x 128 tiles
#define NT3 (SPACK/128)     // 11 N-tiles in gemm3
#define QROWS 22400         // 400*56
#define QPAD 22528          // 176 x 128
#define MFR 3200            // query frames
#define MPAD 3584           // frame-row padding in g_Ah / g_P
#define NVID 425            // 400 query + 25 support videos
#define CMROWS (NVID*6)     // 2550 compact rows per j slice
#define CMPAD 2560          // 20 x 128

// ---------------- MMA smem layout (128x128 CTA tile, K-chunk 64, 3 stages) ----------------
#define TILE_BYTES 16384                   // 128 rows x 128B (64 fp16)
#define STAGE_BYTES (2*TILE_BYTES)         // A + B = 32 KB
#define SMEM_BYTES (3*STAGE_BYTES)         // 96 KB -> 2 CTAs/SM
#define SWZ(o) ((o) ^ (((o) >> 3) & 0x70))

// assembly smem: 24 vectors of 1024 fp32 + 56x8 reduce scratch
#define ASM_SMEM ((24*1024 + TN*8) * 4)

// combinations(range(8),3), lexicographic
__constant__ unsigned char TUP[TN][3] = {
  {0,1,2},{0,1,3},{0,1,4},{0,1,5},{0,1,6},{0,1,7},
  {0,2,3},{0,2,4},{0,2,5},{0,2,6},{0,2,7},
  {0,3,4},{0,3,5},{0,3,6},{0,3,7},
  {0,4,5},{0,4,6},{0,4,7},
  {0,5,6},{0,5,7},{0,6,7},
  {1,2,3},{1,2,4},{1,2,5},{1,2,6},{1,2,7},
  {1,3,4},{1,3,5},{1,3,6},{1,3,7},
  {1,4,5},{1,4,6},{1,4,7},
  {1,5,6},{1,5,7},{1,6,7},
  {2,3,4},{2,3,5},{2,3,6},{2,3,7},
  {2,4,5},{2,4,6},{2,4,7},
  {2,5,6},{2,5,7},{2,6,7},
  {3,4,5},{3,4,6},{3,4,7},
  {3,5,6},{3,5,7},{3,6,7},
  {4,5,6},{4,5,7},{4,6,7},
  {5,6,7}
};

// class -> 3 (tile,half) entries; entry e: tile = e>>1, half = e&1
__constant__ unsigned char CLS_E[NWAY][3] = {
  {0, 2, 4}, {5, 6, 8}, {9, 10, 12}, {13, 14, 16}, {17, 18, 20}
};

// ---------------- scratch (__device__ globals) ----------------
__device__ __align__(256) __half g_Ah[(size_t)MPAD*DIM];          // frames fp16
__device__ __align__(256) __half g_Wh[(size_t)3*DOUT*DIM];        // W rearranged fp16
__device__ __align__(256) float  g_P[(size_t)MPAD*3*DOUT];        // partial embeddings
__device__ __align__(256) __half g_QE[(size_t)QPAD*DOUT];         // query tuple emb fp16
__device__ __align__(256) float  g_q2[QPAD];
__device__ __align__(256) __half g_SE[(size_t)SPACK*DOUT];        // packed support emb
__device__ __align__(256) float  g_s2[SPACK];
__device__ __align__(256) float  g_tmin[2*NT3][QPAD];             // per-(tile,half) row mins
__device__ int g_sloc[NSUP];                                      // support n -> c*SHOT+shotRank

// ---------------- helpers ----------------
__device__ __forceinline__ uint32_t smem_u32(const void* p) {
    uint32_t a;
    asm("{ .reg .u64 t; cvta.to.shared.u64 t, %1; cvt.u32.u64 %0, t; }" : "=r"(a) : "l"(p));
    return a;
}
__device__ __forceinline__ void cp16(uint32_t s, const void* g) {
    asm volatile("cp.async.cg.shared.global [%0], [%1], 16;" :: "r"(s), "l"(g) : "memory");
}
#define LDSM4(r, addr) \
    asm volatile("ldmatrix.sync.aligned.m8n8.x4.shared.b16 {%0,%1,%2,%3}, [%4];" \
        : "=r"((r)[0]), "=r"((r)[1]), "=r"((r)[2]), "=r"((r)[3]) : "r"(addr))
#define MMA_F16(c, a, b0, b1) \
    asm volatile("mma.sync.aligned.m16n8k16.row.col.f32.f16.f16.f32 " \
        "{%0,%1,%2,%3}, {%4,%5,%6,%7}, {%8,%9}, {%0,%1,%2,%3};" \
        : "+f"((c)[0]), "+f"((c)[1]), "+f"((c)[2]), "+f"((c)[3]) \
        : "r"((a)[0]), "r"((a)[1]), "r"((a)[2]), "r"((a)[3]), "r"(b0), "r"(b1))

// ---------------- generic fp16 mainloop pieces ----------------
__device__ __forceinline__ void load_tile(uint32_t sbase, const __half* g,
                                          int stride, int chunk, int tid) {
    const __half* gp = g + (size_t)chunk * 64;
    #pragma unroll
    for (int i = 0; i < 4; i++) {
        int idx = i * 256 + tid;
        int row = idx >> 3, seg = idx & 7;
        cp16(sbase + SWZ(row * 128 + seg * 16), gp + (size_t)row * stride + seg * 8);
    }
}
// gemm1 A loader: compact row c -> source frame row (c/6)*8 + c%6 + j
__device__ __forceinline__ void load_tile_a(uint32_t sbase, int j, int mBase,
                                            int chunk, int tid) {
    const __half* gp = g_Ah + (size_t)chunk * 64;
    #pragma unroll
    for (int i = 0; i < 4; i++) {
        int idx = i * 256 + tid;
        int row = idx >> 3, seg = idx & 7;
        int cr = mBase + row;
        int orig = (cr / 6) * 8 + cr % 6 + j;
        cp16(sbase + SWZ(row * 128 + seg * 16), gp + (size_t)orig * DIM + seg * 8);
    }
}

// lane addressing shared by both mainloops
struct LaneAddr {
    uint32_t aRowB, aXm, aK, bRowB, bXm, bK;
};
__device__ __forceinline__ LaneAddr lane_addr(int tid) {
    const int l = tid & 31;
    const int wm = (tid >> 5) >> 2, wn = (tid >> 5) & 3;
    LaneAddr la;
    la.aRowB = (uint32_t)(wm * 64 + (l & 15)) * 128;
    la.aXm   = (uint32_t)(l & 7) << 4;
    la.aK    = ((l >> 4) & 1) * 16;
    la.bRowB = (uint32_t)(wn * 32 + (l & 7) + ((l >> 4) & 1) * 8) * 128;
    la.bXm   = (uint32_t)(l & 7) << 4;
    la.bK    = ((l >> 3) & 1) * 16;
    return la;
}

__device__ __forceinline__ void chunk_mma(uint32_t st, const LaneAddr& la,
                                          float acc[4][4][4]) {
    #pragma unroll
    for (int kk = 0; kk < 4; kk++) {
        uint32_t a[4][4], b[8];
        const uint32_t ao = ((kk * 32 + la.aK) ^ la.aXm) + la.aRowB;
        const uint32_t bo = ((kk * 32 + la.bK) ^ la.bXm) + la.bRowB + TILE_BYTES;
        #pragma unroll
        for (int mi = 0; mi < 4; mi++) LDSM4(a[mi], st + ao + mi * 2048);
        LDSM4(b + 0, st + bo);
        LDSM4(b + 4, st + bo + 2048);
        #pragma unroll
        for (int mi = 0; mi < 4; mi++)
            #pragma unroll
            for (int ni = 0; ni < 4; ni++)
                MMA_F16(acc[mi][ni], a[mi], b[ni * 2], b[ni * 2 + 1]);
    }
}

// ---------------- merged conversion kernel (+ label decode in block 0) ----------------
__device__ __forceinline__ uint2 pack_half4(float4 r) {
    __half h0 = __float2half_rn(r.x), h1 = __float2half_rn(r.y),
           h2 = __float2half_rn(r.z), h3 = __float2half_rn(r.w);
    uint2 p;
    p.x = (uint32_t)__half_as_ushort(h0) | ((uint32_t)__half_as_ushort(h1) << 16);
    p.y = (uint32_t)__half_as_ushort(h2) | ((uint32_t)__half_as_ushort(h3) << 16);
    return p;
}
__device__ __forceinline__ float sumsq_half4(uint2 p) {
    float f0 = __half2float(__ushort_as_half((unsigned short)(p.x & 0xffff)));
    float f1 = __half2float(__ushort_as_half((unsigned short)(p.x >> 16)));
    float f2 = __half2float(__ushort_as_half((unsigned short)(p.y & 0xffff)));
    float f3 = __half2float(__ushort_as_half((unsigned short)(p.y >> 16)));
    return f0 * f0 + f1 * f1 + f2 * f2 + f3 * f3;
}

#define NQ4 (MFR * DIM / 4)                 // query quads
#define NS4 ((MPAD - MFR) * DIM / 4)        // support + pad quads
#define NW4 (3 * DOUT * DIM / 4)            // W quads

__global__ __launch_bounds__(256) void convAll(const float* __restrict__ q,
                                               const float* __restrict__ s,
                                               const float* __restrict__ W,
                                               const int* __restrict__ raw)
{
    if (blockIdx.x == 0 && threadIdx.x == 0) {
        // label decode (int32 vs int64 auto-detect)
        bool is64 = true;
        for (int i = 1; i < NSUP; i += 2) if (raw[i] != 0) { is64 = false; break; }
        if (is64) for (int i = 0; i < NSUP; i += 2) if (raw[i] < 0 || raw[i] >= NWAY) { is64 = false; break; }
        int cnt[NWAY];
        #pragma unroll
        for (int c = 0; c < NWAY; ++c) cnt[c] = 0;
        for (int i = 0; i < NSUP; ++i) {
            int lab = is64 ? raw[2 * i] : raw[i];
            if (lab >= 0 && lab < NWAY && cnt[lab] < SHOT) {
                g_sloc[i] = lab * SHOT + cnt[lab];
                cnt[lab]++;
            }
        }
    }
    int i = blockIdx.x * 256 + threadIdx.x;
    if (i < NQ4) {
        *(uint2*)(g_Ah + (size_t)i * 4) = pack_half4(((const float4*)q)[i]);
    } else if (i < NQ4 + NS4) {
        i -= NQ4;
        uint2 p = make_uint2(0, 0);
        if (i < NSUP * SEQF * DIM / 4) p = pack_half4(((const float4*)s)[i]);
        *(uint2*)(g_Ah + (size_t)MFR * DIM + (size_t)i * 4) = p;
    } else if (i < NQ4 + NS4 + NW4) {
        i -= NQ4 + NS4;
        size_t e = (size_t)i * 4;
        int k = (int)(e & (DIM - 1));
        size_t r = e >> 11;
        int n = (int)(r & (DOUT - 1));
        int j = (int)(r >> 10);
        float4 x = *(const float4*)(W + (size_t)n * (3 * DIM) + (size_t)j * DIM + k);
        *(uint2*)(g_Wh + e) = pack_half4(x);
    }
}

// ---------------- stage 1: partial-embedding GEMM (compact M per j slice) ----------------
__global__ __launch_bounds__(256, 2) void gemm1()
{
    extern __shared__ char smem[];
    const int nBase = blockIdx.x * 128;
    const int j     = blockIdx.y;
    const int mBase = blockIdx.z * 128;          // compact row base
    const __half* B = g_Wh + ((size_t)j * DOUT + nBase) * DIM;

    float acc[4][4][4];
    #pragma unroll
    for (int a = 0; a < 4; a++)
        #pragma unroll
        for (int b = 0; b < 4; b++)
            #pragma unroll
            for (int c = 0; c < 4; c++) acc[a][b][c] = 0.f;

    const uint32_t sb = smem_u32(smem);
    const int tid = threadIdx.x;
    const LaneAddr la = lane_addr(tid);

    load_tile_a(sb, j, mBase, 0, tid);
    load_tile(sb + TILE_BYTES, B, DIM, 0, tid);
    asm volatile("cp.async.commit_group;" ::: "memory");
    load_tile_a(sb + STAGE_BYTES, j, mBase, 1, tid);
    load_tile(sb + STAGE_BYTES + TILE_BYTES, B, DIM, 1, tid);
    asm volatile("cp.async.commit_group;" ::: "memory");

    const int KC = DIM / 64;
    int stCur = 0, stNxt = 2;
    #pragma unroll 1
    for (int k = 0; k < KC; k++) {
        if (k + 2 < KC) { asm volatile("cp.async.wait_group 1;" ::: "memory"); }
        else            { asm volatile("cp.async.wait_group 0;" ::: "memory"); }
        __syncthreads();
        if (k + 2 < KC) {
            load_tile_a(sb + (uint32_t)stNxt * STAGE_BYTES, j, mBase, k + 2, tid);
            load_tile(sb + (uint32_t)stNxt * STAGE_BYTES + TILE_BYTES, B, DIM, k + 2, tid);
            asm volatile("cp.async.commit_group;" ::: "memory");
        }
        chunk_mma(sb + (uint32_t)stCur * STAGE_BYTES, la, acc);
        stCur = (stCur == 2) ? 0 : stCur + 1;
        stNxt = (stNxt == 2) ? 0 : stNxt + 1;
    }
    __syncthreads();

    const int l = tid & 31;
    const int wm = (tid >> 5) >> 2, wn = (tid >> 5) & 3;
    #pragma unroll
    for (int mi = 0; mi < 4; mi++) {
        const int c0 = mBase + wm * 64 + mi * 16 + (l >> 2);
        const int o0 = (c0 / 6) * 8 + c0 % 6 + j;
        const int c8 = c0 + 8;
        const int o8 = (c8 / 6) * 8 + c8 % 6 + j;
        #pragma unroll
        for (int ni = 0; ni < 4; ni++) {
            const int col = nBase + wn * 32 + ni * 8 + (l & 3) * 2;
            *(float2*)(g_P + ((size_t)o0 * 3 + j) * DOUT + col) =
                make_float2(acc[mi][ni][0], acc[mi][ni][1]);
            *(float2*)(g_P + ((size_t)o8 * 3 + j) * DOUT + col) =
                make_float2(acc[mi][ni][2], acc[mi][ni][3]);
        }
    }
}

// ---------------- stage 2: fused per-video assembly (merged q+s) ----------------
__device__ __forceinline__ void assemble_video(
    const float* __restrict__ srcP,     // 24 rows x 1024 fp32 (contiguous)
    __half* __restrict__ dstE,          // first of 56 output rows
    float* __restrict__ dstN,           // 56 norms
    const float* __restrict__ bias,
    float* sP)                          // smem: 24*1024 + TN*8 floats
{
    const int tid = threadIdx.x;
    float* ws = sP + 24 * DOUT;
    {
        const float4* s = (const float4*)srcP;
        float4* d = (float4*)sP;
        #pragma unroll
        for (int i = 0; i < 24; i++) d[i * 256 + tid] = s[i * 256 + tid];
    }
    __syncthreads();
    const int o = tid * 4;
    const float4 vb = *(const float4*)(bias + o);
    const int l = tid & 31, wid = tid >> 5;
    #pragma unroll 4
    for (int t = 0; t < TN; t++) {
        const int f0 = TUP[t][0], f1 = TUP[t][1], f2 = TUP[t][2];
        float4 v0 = *(const float4*)(sP + (f0 * 3 + 0) * DOUT + o);
        float4 v1 = *(const float4*)(sP + (f1 * 3 + 1) * DOUT + o);
        float4 v2 = *(const float4*)(sP + (f2 * 3 + 2) * DOUT + o);
        float4 r;
        r.x = fmaxf(v0.x + v1.x + v2.x + vb.x, 0.f);
        r.y = fmaxf(v0.y + v1.y + v2.y + vb.y, 0.f);
        r.z = fmaxf(v0.z + v1.z + v2.z + vb.z, 0.f);
        r.w = fmaxf(v0.w + v1.w + v2.w + vb.w, 0.f);
        uint2 p = pack_half4(r);
        *(uint2*)(dstE + (size_t)t * DOUT + o) = p;
        float ss = sumsq_half4(p);
        #pragma unroll
        for (int s = 16; s > 0; s >>= 1) ss += __shfl_xor_sync(0xffffffffu, ss, s);
        if (l == 0) ws[t * 8 + wid] = ss;
    }
    __syncthreads();
    if (tid < TN) {
        float s = 0.f;
        #pragma unroll
        for (int i = 0; i < 8; i++) s += ws[tid * 8 + i];
        dstN[tid] = s;
    }
}

// grid: [0..NQ) queries | NQ q-pad | (NQ, NQ+NSUP] supports | NQ+NSUP+1 s-pad
__global__ __launch_bounds__(256) void assembleQS(const float* __restrict__ bias)
{
    extern __shared__ float sP[];
    const int b = blockIdx.x;
    const int tid = threadIdx.x;
    if (b < NQ) {
        assemble_video(g_P + (size_t)b * 24 * DOUT,
                       g_QE + (size_t)b * TN * DOUT,
                       g_q2 + b * TN, bias, sP);
    } else if (b == NQ) {      // query pad rows
        for (int i = tid; i < (QPAD - QROWS) * DOUT / 4; i += 256)
            *(uint2*)(g_QE + (size_t)QROWS * DOUT + (size_t)i * 4) = make_uint2(0, 0);
        for (int i = tid; i < QPAD - QROWS; i += 256) g_q2[QROWS + i] = 0.f;
    } else if (b <= NQ + NSUP) {
        const int n = b - NQ - 1;
        const int loc = g_sloc[n];                    // c*SHOT + shotRank
        const int base = (loc / SHOT) * SACT + (loc % SHOT) * TN;
        assemble_video(g_P + (size_t)(MFR + n * SEQF) * 3 * DOUT,
                       g_SE + (size_t)base * DOUT,
                       g_s2 + base, bias, sP);
    } else {                   // support pad cols 1400..1407
        for (int i = tid; i < (SPACK - NWAY * SACT) * DOUT / 4; i += 256)
            *(uint2*)(g_SE + (size_t)NWAY * SACT * DOUT + (size_t)i * 4) = make_uint2(0, 0);
        if (tid < SPACK - NWAY * SACT) g_s2[NWAY * SACT + tid] = 1e30f;
    }
}

// ---------------- stage 3: fused distance GEMM + per-tile class-half min ----------------
__global__ __launch_bounds__(256, 2) void gemm3()
{
    extern __shared__ char smem[];
    __shared__ float s2s[128];
    __shared__ float rowmin[128][4][2];
    const int nt    = blockIdx.x;                // packed support tile
    const int nBase = nt * 128;
    const int mBase = blockIdx.y * 128;
    const int tid = threadIdx.x, l = tid & 31;
    const int wm = (tid >> 5) >> 2, wn = (tid >> 5) & 3;

    if (tid < 128) s2s[tid] = g_s2[nBase + tid];

    const __half* A = g_QE + (size_t)mBase * DOUT;
    const __half* B = g_SE + (size_t)nBase * DOUT;

    float acc[4][4][4];
    #pragma unroll
    for (int a = 0; a < 4; a++)
        #pragma unroll
        for (int b = 0; b < 4; b++)
            #pragma unroll
            for (int d = 0; d < 4; d++) acc[a][b][d] = 0.f;

    const uint32_t sb = smem_u32(smem);
    const LaneAddr la = lane_addr(tid);

    load_tile(sb, A, DOUT, 0, tid);
    load_tile(sb + TILE_BYTES, B, DOUT, 0, tid);
    asm volatile("cp.async.commit_group;" ::: "memory");
    load_tile(sb + STAGE_BYTES, A, DOUT, 1, tid);
    load_tile(sb + STAGE_BYTES + TILE_BYTES, B, DOUT, 1, tid);
    asm volatile("cp.async.commit_group;" ::: "memory");

    const int KC = DOUT / 64;
    int stCur = 0, stNxt = 2;
    #pragma unroll 1
    for (int k = 0; k < KC; k++) {
        if (k + 2 < KC) { asm volatile("cp.async.wait_group 1;" ::: "memory"); }
        else            { asm volatile("cp.async.wait_group 0;" ::: "memory"); }
        __syncthreads();
        if (k + 2 < KC) {
            load_tile(sb + (uint32_t)stNxt * STAGE_BYTES, A, DOUT, k + 2, tid);
            load_tile(sb + (uint32_t)stNxt * STAGE_BYTES + TILE_BYTES, B, DOUT, k + 2, tid);
            asm volatile("cp.async.commit_group;" ::: "memory");
        }
        chunk_mma(sb + (uint32_t)stCur * STAGE_BYTES, la, acc);
        stCur = (stCur == 2) ? 0 : stCur + 1;
        stNxt = (stNxt == 2) ? 0 : stNxt + 1;
    }
    __syncthreads();

    // segmented epilogue: tile spans at most 2 classes (boundary is even)
    const int cLo = min(nBase / SACT, NWAY - 1);
    float mnL0[4], mnL1[4], mnH0[4], mnH1[4];
    #pragma unroll
    for (int mi = 0; mi < 4; mi++) { mnL0[mi] = 3e38f; mnL1[mi] = 3e38f; mnH0[mi] = 3e38f; mnH1[mi] = 3e38f; }
    #pragma unroll
    for (int ni = 0; ni < 4; ni++) {
        const int col = wn * 32 + ni * 8 + (l & 3) * 2;
        const bool isHi = (min((nBase + col) / SACT, NWAY - 1) != cLo);
        const float sa = s2s[col], sbv = s2s[col + 1];
        #pragma unroll
        for (int mi = 0; mi < 4; mi++) {
            float v0 = fminf(fmaf(-2.f, acc[mi][ni][0], sa), fmaf(-2.f, acc[mi][ni][1], sbv));
            float v1 = fminf(fmaf(-2.f, acc[mi][ni][2], sa), fmaf(-2.f, acc[mi][ni][3], sbv));
            if (isHi) { mnH0[mi] = fminf(mnH0[mi], v0); mnH1[mi] = fminf(mnH1[mi], v1); }
            else      { mnL0[mi] = fminf(mnL0[mi], v0); mnL1[mi] = fminf(mnL1[mi], v1); }
        }
    }
    #pragma unroll
    for (int mi = 0; mi < 4; mi++) {
        #pragma unroll
        for (int s = 1; s <= 2; s <<= 1) {
            mnL0[mi] = fminf(mnL0[mi], __shfl_xor_sync(0xffffffffu, mnL0[mi], s));
            mnL1[mi] = fminf(mnL1[mi], __shfl_xor_sync(0xffffffffu, mnL1[mi], s));
            mnH0[mi] = fminf(mnH0[mi], __shfl_xor_sync(0xffffffffu, mnH0[mi], s));
            mnH1[mi] = fminf(mnH1[mi], __shfl_xor_sync(0xffffffffu, mnH1[mi], s));
        }
    }
    if ((l & 3) == 0) {
        #pragma unroll
        for (int mi = 0; mi < 4; mi++) {
            const int r0 = wm * 64 + mi * 16 + (l >> 2);
            rowmin[r0][wn][0] = mnL0[mi];      rowmin[r0][wn][1] = mnH0[mi];
            rowmin[r0 + 8][wn][0] = mnL1[mi];  rowmin[r0 + 8][wn][1] = mnH1[mi];
        }
    }
    __syncthreads();
    if (tid < 128) {
        float mL = fminf(fminf(rowmin[tid][0][0], rowmin[tid][1][0]),
                         fminf(rowmin[tid][2][0], rowmin[tid][3][0]));
        float mH = fminf(fminf(rowmin[tid][0][1], rowmin[tid][1][1]),
                         fminf(rowmin[tid][2][1], rowmin[tid][3][1]));
        g_tmin[2 * nt + 0][mBase + tid] = mL;
        g_tmin[2 * nt + 1][mBase + tid] = mH;
    }
}

// ---------------- stage 4: finalize ----------------
__global__ void finalize(float* __restrict__ out)
{
    int idx = blockIdx.x * blockDim.x + threadIdx.x;
    if (idx >= NQ * NWAY) return;
    int q = idx / NWAY, c = idx % NWAY;
    const int e0 = CLS_E[c][0], e1 = CLS_E[c][1], e2 = CLS_E[c][2];
    float s = 0.f;
    #pragma unroll 8
    for (int t = 0; t < TN; ++t) {
        const int row = q * TN + t;
        float m = fminf(fminf(g_tmin[e0][row], g_tmin[e1][row]), g_tmin[e2][row]);
        s += sqrtf(fmaxf(g_q2[row] + m, 0.f));
    }
    out[q * NWAY + c] = -s * (1.0f / (float)TN);
}

// ---------------- launch ----------------
extern "C" void kernel_launch(void* const* d_in, const int* in_sizes, int n_in,
                              void* d_out, int out_size)
{
    const float* support = (const float*)d_in[0];      // [25,8,2048]
    const int*   labraw  = (const int*)d_in[1];        // [25] int32/int64
    const float* queries = (const float*)d_in[2];      // [400,8,2048]
    const float* W       = (const float*)d_in[3];      // [1024,6144]
    const float* bias    = (const float*)d_in[4];      // [1024]
    float*       out     = (float*)d_out;              // [400,5]
    (void)in_sizes; (void)n_in; (void)out_size;

    cudaFuncSetAttribute(gemm1, cudaFuncAttributeMaxDynamicSharedMemorySize, SMEM_BYTES);
    cudaFuncSetAttribute(gemm3, cudaFuncAttributeMaxDynamicSharedMemorySize, SMEM_BYTES);
    cudaFuncSetAttribute(assembleQS, cudaFuncAttributeMaxDynamicSharedMemorySize, ASM_SMEM);

    convAll<<<(NQ4 + NS4 + NW4 + 255) / 256, 256>>>(queries, support, W, labraw);

    gemm1<<<dim3(DOUT / 128, 3, CMPAD / 128), 256, SMEM_BYTES>>>();

    assembleQS<<<NQ + NSUP + 2, 256, ASM_SMEM>>>(bias);

    gemm3<<<dim3(NT3, QPAD / 128), 256, SMEM_BYTES>>>();

    finalize<<<(NQ * NWAY + 255) / 256, 256>>>(out);
}